// round 1
// baseline (speedup 1.0000x reference)
#include <cuda_runtime.h>
#include <math.h>

// x: [32, 16, 512, 512] fp32. Stats over spatial dims per (b, c).
// out: [32, 64] = concat(mean[16], std[16], max[16], min[16]) per batch row.

static constexpr int HW     = 512 * 512;   // 262144 elements per channel
static constexpr int N4     = HW / 4;      // 65536 float4 per channel
static constexpr int NTHR   = 256;
static constexpr int NCHAN  = 32 * 16;     // 512 CTAs, one per (b,c)

__global__ __launch_bounds__(NTHR, 1)
void image_stats_kernel(const float* __restrict__ x, float* __restrict__ out) {
    const int bc = blockIdx.x;          // 0..511
    const int b  = bc >> 4;
    const int c  = bc & 15;

    const float4* __restrict__ p =
        reinterpret_cast<const float4*>(x + (size_t)bc * HW);

    float sum   = 0.0f;
    float sumsq = 0.0f;
    float mx    = -INFINITY;
    float mn    =  INFINITY;

    // Coalesced streaming: thread t reads float4 at t, t+256, ...
    // unroll 4 -> 4 independent LDG.128 in flight per thread.
    #pragma unroll 4
    for (int i = threadIdx.x; i < N4; i += NTHR) {
        float4 v = p[i];
        sum   += (v.x + v.y) + (v.z + v.w);
        sumsq  = fmaf(v.x, v.x, sumsq);
        sumsq  = fmaf(v.y, v.y, sumsq);
        sumsq  = fmaf(v.z, v.z, sumsq);
        sumsq  = fmaf(v.w, v.w, sumsq);
        mx = fmaxf(mx, fmaxf(fmaxf(v.x, v.y), fmaxf(v.z, v.w)));
        mn = fminf(mn, fminf(fminf(v.x, v.y), fminf(v.z, v.w)));
    }

    // Warp reduction
    #pragma unroll
    for (int o = 16; o > 0; o >>= 1) {
        sum   += __shfl_xor_sync(0xffffffffu, sum,   o);
        sumsq += __shfl_xor_sync(0xffffffffu, sumsq, o);
        mx = fmaxf(mx, __shfl_xor_sync(0xffffffffu, mx, o));
        mn = fminf(mn, __shfl_xor_sync(0xffffffffu, mn, o));
    }

    __shared__ float s_sum[8], s_sq[8], s_mx[8], s_mn[8];
    const int wid = threadIdx.x >> 5;
    const int lid = threadIdx.x & 31;
    if (lid == 0) {
        s_sum[wid] = sum;
        s_sq[wid]  = sumsq;
        s_mx[wid]  = mx;
        s_mn[wid]  = mn;
    }
    __syncthreads();

    if (threadIdx.x == 0) {
        float ts = 0.0f, tq = 0.0f, tmx = -INFINITY, tmn = INFINITY;
        #pragma unroll
        for (int w = 0; w < 8; w++) {
            ts += s_sum[w];
            tq += s_sq[w];
            tmx = fmaxf(tmx, s_mx[w]);
            tmn = fminf(tmn, s_mn[w]);
        }
        const float mean = ts / (float)HW;
        // unbiased variance: (sum(x^2) - sum(x)*mean) / (N-1)
        const float var  = (tq - ts * mean) / (float)(HW - 1);
        const float sd   = sqrtf(fmaxf(var, 0.0f));

        float* __restrict__ ob = out + (size_t)b * 64;
        ob[c]      = mean;
        ob[16 + c] = sd;
        ob[32 + c] = tmx;
        ob[48 + c] = tmn;
    }
}

extern "C" void kernel_launch(void* const* d_in, const int* in_sizes, int n_in,
                              void* d_out, int out_size) {
    const float* x = (const float*)d_in[0];
    float* out = (float*)d_out;
    image_stats_kernel<<<NCHAN, NTHR>>>(x, out);
}